// round 6
// baseline (speedup 1.0000x reference)
#include <cuda_runtime.h>

#define NB      1024
#define NNODES  10
#define FIN     2048
#define FOUT    128
#define NHEADS  8
#define MTOT    (NB * NNODES)   // 10240
#define KSPLIT  8
#define KCHUNK  (FIN / KSPLIT)  // 256
#define GB      2               // batches per fused CTA (20 rows used, 32-row GEMM tile)
#define ROWS_U  (GB * NNODES)   // 20 used rows per fused CTA

// Scratch (allocation-guard-safe __device__ globals)
__device__ float g_part[KSPLIT][MTOT * FOUT];        // 42 MB split-K partials
__device__ float g_emb[(MTOT + 64) * FOUT];          // 5.2 MB (+pad for tile overrun)

// ---------------------------------------------------------------------------
// helpers
// ---------------------------------------------------------------------------
__device__ __forceinline__ float tf32r(float x) {
    unsigned y;
    asm("cvt.rna.tf32.f32 %0, %1;" : "=r"(y) : "f"(x));
    return __uint_as_float(y);
}
__device__ __forceinline__ float4 tf32r4(float4 v) {
    v.x = tf32r(v.x); v.y = tf32r(v.y); v.z = tf32r(v.z); v.w = tf32r(v.w);
    return v;
}
__device__ __forceinline__ void mma1688(float* c, const unsigned* a, unsigned b0, unsigned b1) {
    asm volatile(
        "mma.sync.aligned.m16n8k8.row.col.f32.tf32.tf32.f32 "
        "{%0,%1,%2,%3}, {%4,%5,%6,%7}, {%8,%9}, {%0,%1,%2,%3};"
        : "+f"(c[0]), "+f"(c[1]), "+f"(c[2]), "+f"(c[3])
        : "r"(a[0]), "r"(a[1]), "r"(a[2]), "r"(a[3]), "r"(b0), "r"(b1));
}

// ---------------------------------------------------------------------------
// TF32 MMA GEMM core (32 x 128 tile, K chunked by 32): proven fragment map.
// As stride 36 / Bs stride 136 -> conflict-free. Register double-buffer.
// ---------------------------------------------------------------------------
template <int NCHUNK>
__device__ __forceinline__ void gemm_core(const float* __restrict__ Ag, int lda,
                                          const float* __restrict__ Bg,
                                          const float* __restrict__ bias,
                                          float* __restrict__ Cg, int m0) {
    __shared__ __align__(16) float As[32 * 36];
    __shared__ __align__(16) float Bs[32 * 136];

    const int tid  = threadIdx.x;
    const int lane = tid & 31;
    const int warp = tid >> 5;
    const int g    = lane >> 2;
    const int t    = lane & 3;

    float4 pa[2], pb[8];

    auto loadAB = [&](int k0) {
#pragma unroll
        for (int i = 0; i < 2; i++) {
            int idx = tid + 128 * i;
            int m = idx >> 3, c4 = idx & 7;
            pa[i] = *(const float4*)(Ag + (size_t)(m0 + m) * lda + k0 + c4 * 4);
        }
#pragma unroll
        for (int i = 0; i < 8; i++) {
            int idx = tid + 128 * i;
            int r = idx >> 5, n4 = idx & 31;
            pb[i] = *(const float4*)(Bg + (size_t)(k0 + r) * FOUT + n4 * 4);
        }
    };
    auto stsAB = [&]() {
#pragma unroll
        for (int i = 0; i < 2; i++) {
            int idx = tid + 128 * i;
            int m = idx >> 3, c4 = idx & 7;
            *(float4*)(As + m * 36 + c4 * 4) = tf32r4(pa[i]);
        }
#pragma unroll
        for (int i = 0; i < 8; i++) {
            int idx = tid + 128 * i;
            int r = idx >> 5, n4 = idx & 31;
            *(float4*)(Bs + r * 136 + n4 * 4) = tf32r4(pb[i]);
        }
    };

    float acc[2][4][4];
#pragma unroll
    for (int mt = 0; mt < 2; mt++)
#pragma unroll
        for (int nt = 0; nt < 4; nt++)
#pragma unroll
            for (int q = 0; q < 4; q++) acc[mt][nt][q] = 0.f;

    auto compute = [&]() {
#pragma unroll
        for (int ks = 0; ks < 4; ks++) {
            unsigned a[2][4];
#pragma unroll
            for (int mt = 0; mt < 2; mt++) {
                const float* ap = As + (mt * 16 + g) * 36 + ks * 8 + t;
                a[mt][0] = __float_as_uint(ap[0]);
                a[mt][1] = __float_as_uint(ap[288]);
                a[mt][2] = __float_as_uint(ap[4]);
                a[mt][3] = __float_as_uint(ap[292]);
            }
#pragma unroll
            for (int nt = 0; nt < 4; nt++) {
                const float* bp_ = Bs + (ks * 8 + t) * 136 + warp * 32 + nt * 8 + g;
                unsigned b0 = __float_as_uint(bp_[0]);
                unsigned b1 = __float_as_uint(bp_[544]);
#pragma unroll
                for (int mt = 0; mt < 2; mt++) mma1688(acc[mt][nt], a[mt], b0, b1);
            }
        }
    };

    loadAB(0);
    stsAB();
    __syncthreads();
    for (int ch = 1; ch < NCHUNK; ch++) {
        loadAB(ch * 32);
        compute();
        __syncthreads();
        stsAB();
        __syncthreads();
    }
    compute();

#pragma unroll
    for (int mt = 0; mt < 2; mt++) {
#pragma unroll
        for (int nt = 0; nt < 4; nt++) {
            int col = warp * 32 + nt * 8 + 2 * t;
            float bb0 = bias ? bias[col] : 0.f;
            float bb1 = bias ? bias[col + 1] : 0.f;
            int row = m0 + mt * 16 + g;
            float2 v0 = make_float2(acc[mt][nt][0] + bb0, acc[mt][nt][1] + bb1);
            float2 v1 = make_float2(acc[mt][nt][2] + bb0, acc[mt][nt][3] + bb1);
            *(float2*)(Cg + (size_t)row * FOUT + col)       = v0;
            *(float2*)(Cg + (size_t)(row + 8) * FOUT + col) = v1;
        }
    }
}

// K1: split-K partials of emb = x @ Wp (+bp on split 0)
__global__ __launch_bounds__(128) void k_gemm_emb(const float* __restrict__ x,
                                                  const float* __restrict__ Wp,
                                                  const float* __restrict__ bp) {
    const int ks = blockIdx.y;
    const float* Ag   = x + (size_t)ks * KCHUNK;
    const float* Bg   = Wp + (size_t)ks * KCHUNK * FOUT;
    const float* bias = (ks == 0) ? bp : nullptr;
    gemm_core<KCHUNK / 32>(Ag, FIN, Bg, bias, g_part[ks], blockIdx.x * 32);
}

// K1b: g_emb = sum of the 8 split-K partials
__global__ __launch_bounds__(256) void k_reduce8() {
    int i = (blockIdx.x * 256 + threadIdx.x) * 4;
    float4 s = *(const float4*)(g_part[0] + i);
#pragma unroll
    for (int p = 1; p < KSPLIT; p++) {
        float4 v = *(const float4*)(g_part[p] + i);
        s.x += v.x; s.y += v.y; s.z += v.z; s.w += v.w;
    }
    *(float4*)(g_emb + i) = s;
}

// ---------------------------------------------------------------------------
// K2 (fused): per (batch-pair bg, head h):
//   A = emb[rows] @ W1[h][0:128]   + b1[h]   -> smem Aout[20][132]
//   C = emb[rows] @ W1[h][128:256]           -> smem Cout[20][132]
//   S(i,k) = sum_f leaky(A[i][f]+C[k][f]) * W2[h][f] + b2[h]
//   out[b,h,j,i] = S(i, j+(j>=i)) for j<9;  out[b,h,9,:] = 0
// 128 threads; GEMM tile M=32 covers 20 used rows. NO smem aliasing:
// Aout + Cout + tiles = 42.1 KB static.
// ---------------------------------------------------------------------------
__global__ __launch_bounds__(128) void k_fused(const float* __restrict__ W1,
                                               const float* __restrict__ b1,
                                               const float* __restrict__ W2,
                                               const float* __restrict__ b2,
                                               float* __restrict__ out) {
    __shared__ __align__(16) float As[32 * 36];      // 4.5 KB
    __shared__ __align__(16) float Bs[32 * 136];     // 17.4 KB
    __shared__ __align__(16) float Aout[ROWS_U * 132];  // 10.3 KB
    __shared__ __align__(16) float Cout[ROWS_U * 132];  // 10.3 KB

    const int tid  = threadIdx.x;
    const int lane = tid & 31;
    const int warp = tid >> 5;
    const int g    = lane >> 2;
    const int t    = lane & 3;

    const int m0 = blockIdx.x * ROWS_U;   // global row base (20 per CTA)
    const int h  = blockIdx.y;

    float4 pa[2], pb[8];
    const float* Bg;

    auto loadAB = [&](int k0) {
#pragma unroll
        for (int i = 0; i < 2; i++) {
            int idx = tid + 128 * i;
            int m = idx >> 3, c4 = idx & 7;
            pa[i] = *(const float4*)(g_emb + (size_t)(m0 + m) * FOUT + k0 + c4 * 4);
        }
#pragma unroll
        for (int i = 0; i < 8; i++) {
            int idx = tid + 128 * i;
            int r = idx >> 5, n4 = idx & 31;
            pb[i] = *(const float4*)(Bg + (size_t)(k0 + r) * FOUT + n4 * 4);
        }
    };
    auto stsAB = [&]() {
#pragma unroll
        for (int i = 0; i < 2; i++) {
            int idx = tid + 128 * i;
            int m = idx >> 3, c4 = idx & 7;
            *(float4*)(As + m * 36 + c4 * 4) = tf32r4(pa[i]);
        }
#pragma unroll
        for (int i = 0; i < 8; i++) {
            int idx = tid + 128 * i;
            int r = idx >> 5, n4 = idx & 31;
            *(float4*)(Bs + r * 136 + n4 * 4) = tf32r4(pb[i]);
        }
    };

    float acc[2][4][4];
    auto zero_acc = [&]() {
#pragma unroll
        for (int mt = 0; mt < 2; mt++)
#pragma unroll
            for (int nt = 0; nt < 4; nt++)
#pragma unroll
                for (int q = 0; q < 4; q++) acc[mt][nt][q] = 0.f;
    };
    auto compute = [&]() {
#pragma unroll
        for (int ks = 0; ks < 4; ks++) {
            unsigned a[2][4];
#pragma unroll
            for (int mt = 0; mt < 2; mt++) {
                const float* ap = As + (mt * 16 + g) * 36 + ks * 8 + t;
                a[mt][0] = __float_as_uint(ap[0]);
                a[mt][1] = __float_as_uint(ap[288]);
                a[mt][2] = __float_as_uint(ap[4]);
                a[mt][3] = __float_as_uint(ap[292]);
            }
#pragma unroll
            for (int nt = 0; nt < 4; nt++) {
                const float* bp_ = Bs + (ks * 8 + t) * 136 + warp * 32 + nt * 8 + g;
                unsigned b0 = __float_as_uint(bp_[0]);
                unsigned b1 = __float_as_uint(bp_[544]);
#pragma unroll
                for (int mt = 0; mt < 2; mt++) mma1688(acc[mt][nt], a[mt], b0, b1);
            }
        }
    };

    // two GEMM phases: half 0 -> Aout (+b1), half 1 -> Cout
    for (int half = 0; half < 2; half++) {
        Bg = W1 + (size_t)(h * 2 * FOUT + half * FOUT) * FOUT;
        zero_acc();
        loadAB(0);
        __syncthreads();            // prior phase's As/Bs reads complete before overwrite
        stsAB();
        __syncthreads();
        for (int ch = 1; ch < 4; ch++) {
            loadAB(ch * 32);
            compute();
            __syncthreads();
            stsAB();
            __syncthreads();
        }
        compute();

        float* dst = (half == 0) ? Aout : Cout;
#pragma unroll
        for (int mt = 0; mt < 2; mt++) {
#pragma unroll
            for (int nt = 0; nt < 4; nt++) {
                int col = warp * 32 + nt * 8 + 2 * t;
                float bb0 = 0.f, bb1 = 0.f;
                if (half == 0) {
                    bb0 = b1[h * FOUT + col];
                    bb1 = b1[h * FOUT + col + 1];
                }
                int row = mt * 16 + g;
                if (row < ROWS_U)
                    *(float2*)(dst + row * 132 + col) =
                        make_float2(acc[mt][nt][0] + bb0, acc[mt][nt][1] + bb1);
                if (row + 8 < ROWS_U)
                    *(float2*)(dst + (row + 8) * 132 + col) =
                        make_float2(acc[mt][nt][2] + bb0, acc[mt][nt][3] + bb1);
            }
        }
    }
    __syncthreads();

    // ---- pair scoring: GB*90 pairs, warp per pair, float4 lanes ----
    const float4 w2v = *(const float4*)(W2 + h * FOUT + lane * 4);
    const float  b2v = b2[h];
    const int    bb  = blockIdx.x * GB;

    for (int p = warp; p < GB * 90; p += 4) {
        int lb = p / 90, pp = p - lb * 90;
        int i  = pp / 9;
        int kk = pp - i * 9;               // output row j
        int k  = kk + (kk >= i);           // source node
        float4 av = *(const float4*)(Aout + (lb * NNODES + i) * 132 + lane * 4);
        float4 cv = *(const float4*)(Cout + (lb * NNODES + k) * 132 + lane * 4);
        float v0 = av.x + cv.x, v1 = av.y + cv.y, v2 = av.z + cv.z, v3 = av.w + cv.w;
        v0 = (v0 > 0.f) ? v0 : 0.2f * v0;
        v1 = (v1 > 0.f) ? v1 : 0.2f * v1;
        v2 = (v2 > 0.f) ? v2 : 0.2f * v2;
        v3 = (v3 > 0.f) ? v3 : 0.2f * v3;
        float s = v0 * w2v.x + v1 * w2v.y + v2 * w2v.z + v3 * w2v.w;
#pragma unroll
        for (int off = 16; off; off >>= 1) s += __shfl_xor_sync(0xffffffffu, s, off);
        if (lane == 0)
            out[((size_t)(bb + lb) * NHEADS + h) * 100 + kk * 10 + i] = s + b2v;
    }
    // zero row 9 of each batch in the group
    if (tid < GB * 10) {
        int lb = tid / 10, ii = tid - lb * 10;
        out[((size_t)(bb + lb) * NHEADS + h) * 100 + 90 + ii] = 0.f;
    }
}

// ---------------------------------------------------------------------------
// Launch. inputs: 0 object_features, 1 scene_geometry(unused), 2 Wp, 3 bp,
//                 4 W1, 5 b1, 6 W2, 7 b2, 8 d_max
// ---------------------------------------------------------------------------
extern "C" void kernel_launch(void* const* d_in, const int* in_sizes, int n_in,
                              void* d_out, int out_size) {
    const float* x  = (const float*)d_in[0];
    const float* Wp = (const float*)d_in[2];
    const float* bp = (const float*)d_in[3];
    const float* W1 = (const float*)d_in[4];
    const float* b1 = (const float*)d_in[5];
    const float* W2 = (const float*)d_in[6];
    const float* b2 = (const float*)d_in[7];
    float* out = (float*)d_out;

    dim3 g1(MTOT / 32, KSPLIT);
    k_gemm_emb<<<g1, 128>>>(x, Wp, bp);

    k_reduce8<<<MTOT * FOUT / (256 * 4), 256>>>();

    dim3 g2(NB / GB, NHEADS);
    k_fused<<<g2, 128>>>(W1, b1, W2, b2, out);
}

// round 10
// speedup vs baseline: 1.2214x; 1.2214x over previous
#include <cuda_runtime.h>
#include <cuda_fp16.h>
#include <cstdint>

#define NB      1024
#define NNODES  10
#define FIN     2048
#define FOUT    128
#define NHEADS  8
#define MTOT    (NB * NNODES)     // 10240
#define KSPLIT  4
#define KCHUNK  (FIN / KSPLIT)    // 512

// Scratch (allocation-guard-safe __device__ globals)
__device__ float  g_part[KSPLIT][MTOT * FOUT];   // 21 MB split-K partials
__device__ float  g_emb[MTOT * FOUT];            // 5.2 MB
__device__ float  g_AC[16][MTOT * FOUT];         // 84 MB: [z][m][f], z = 2h+half
__device__ __half g_WpTh[FOUT * FIN];            // Wp^T  [n=128][k=2048], half
__device__ __half g_W1Th[16][FOUT * FOUT];       // W1^T  [z][f=128][k=128], half

// ---------------------------------------------------------------------------
// helpers
// ---------------------------------------------------------------------------
__device__ __forceinline__ uint32_t smem_u32(const void* p) {
    return (uint32_t)__cvta_generic_to_shared(p);
}
__device__ __forceinline__ uint4 f8_to_h8(float4 a, float4 b) {
    __half2 h0 = __float22half2_rn(make_float2(a.x, a.y));
    __half2 h1 = __float22half2_rn(make_float2(a.z, a.w));
    __half2 h2 = __float22half2_rn(make_float2(b.x, b.y));
    __half2 h3 = __float22half2_rn(make_float2(b.z, b.w));
    uint4 r;
    r.x = *(uint32_t*)&h0; r.y = *(uint32_t*)&h1;
    r.z = *(uint32_t*)&h2; r.w = *(uint32_t*)&h3;
    return r;
}
__device__ __forceinline__ void mma16816(float* c, const uint32_t* a,
                                         uint32_t b0, uint32_t b1) {
    asm volatile(
        "mma.sync.aligned.m16n8k16.row.col.f32.f16.f16.f32 "
        "{%0,%1,%2,%3}, {%4,%5,%6,%7}, {%8,%9}, {%0,%1,%2,%3};"
        : "+f"(c[0]), "+f"(c[1]), "+f"(c[2]), "+f"(c[3])
        : "r"(a[0]), "r"(a[1]), "r"(a[2]), "r"(a[3]), "r"(b0), "r"(b1));
}
#define LDMX4(r0, r1, r2, r3, addr) \
    asm volatile("ldmatrix.sync.aligned.m8n8.x4.shared.b16 {%0,%1,%2,%3}, [%4];" \
        : "=r"(r0), "=r"(r1), "=r"(r2), "=r"(r3) : "r"(addr))

// ---------------------------------------------------------------------------
// FP16 MMA GEMM core: C[m0:m0+32][0:128] (+bias) = A(f32)[m0:][k-span] @ Bh^T
// A [m][k] f32 gmem (converted inline); Bh [n=128][k] half gmem.
// 128 threads, 4 warps n-split (warptile 32x32), BK=32, NCH chunks.
// Smem rows padded to 40 halves (80B): ldmatrix banks (i*20)%32 all distinct
// -> conflict-free. Register double-buffer prefetch.
// Fragments (m16n8k16): per warp per chunk: 4x ldmatrix.x4, 16 MMAs.
// ---------------------------------------------------------------------------
template <int NCH>
__device__ __forceinline__ void gemm_fp16(const float* __restrict__ Ag, int lda,
                                          const __half* __restrict__ Bh, int ldb,
                                          int k0base, int m0,
                                          const float* __restrict__ bias,
                                          float* __restrict__ Cg) {
    __shared__ __align__(16) __half As[32 * 40];     // 2.5 KB
    __shared__ __align__(16) __half Bs[128 * 40];    // 10 KB

    const int tid  = threadIdx.x;
    const int lane = tid & 31;
    const int warp = tid >> 5;
    const int g    = lane >> 2;
    const int t    = lane & 3;

    // tile-fill mapping: thread e covers row e>>2, halves (e&3)*8 .. +7
    const int fr  = tid >> 2;          // 0..31
    const int fc8 = (tid & 3) * 8;     // 0,8,16,24

    // ldmatrix lane->row/koff (in halves)
    const int a_row  = (lane & 7) + ((lane >> 3) & 1) * 8;
    const int a_koff = ((lane >> 4) & 1) * 8;
    const int b_row  = (lane & 7) + ((lane >> 4) & 1) * 8;
    const int b_koff = ((lane >> 3) & 1) * 8;

    float4 pa0, pa1;
    uint4  pb[4];

    auto loadAB = [&](int k0) {
        const float* p = Ag + (size_t)(m0 + fr) * lda + k0 + fc8;
        pa0 = *(const float4*)p;
        pa1 = *(const float4*)(p + 4);
#pragma unroll
        for (int i = 0; i < 4; i++) {
            int e = tid + 128 * i;
            int r = e >> 2, c8 = (e & 3) * 8;
            pb[i] = *(const uint4*)(Bh + (size_t)r * ldb + k0 + c8);
        }
    };
    auto stsAB = [&]() {
        *(uint4*)(As + fr * 40 + fc8) = f8_to_h8(pa0, pa1);
#pragma unroll
        for (int i = 0; i < 4; i++) {
            int e = tid + 128 * i;
            int r = e >> 2, c8 = (e & 3) * 8;
            *(uint4*)(Bs + r * 40 + c8) = pb[i];
        }
    };

    float acc[2][4][4];
#pragma unroll
    for (int mt = 0; mt < 2; mt++)
#pragma unroll
        for (int nt = 0; nt < 4; nt++)
#pragma unroll
            for (int q = 0; q < 4; q++) acc[mt][nt][q] = 0.f;

    auto compute = [&]() {
#pragma unroll
        for (int ks = 0; ks < 2; ks++) {           // 2 k-steps of 16
            uint32_t a[2][4];
#pragma unroll
            for (int mt = 0; mt < 2; mt++) {
                uint32_t addr = smem_u32(As + (mt * 16 + a_row) * 40 + ks * 16 + a_koff);
                LDMX4(a[mt][0], a[mt][1], a[mt][2], a[mt][3], addr);
            }
#pragma unroll
            for (int nt2 = 0; nt2 < 2; nt2++) {
                uint32_t b[4];
                uint32_t addr = smem_u32(Bs + (warp * 32 + nt2 * 16 + b_row) * 40
                                            + ks * 16 + b_koff);
                LDMX4(b[0], b[1], b[2], b[3], addr);
#pragma unroll
                for (int sub = 0; sub < 2; sub++)
#pragma unroll
                    for (int mt = 0; mt < 2; mt++)
                        mma16816(acc[mt][nt2 * 2 + sub], a[mt],
                                 b[sub * 2], b[sub * 2 + 1]);
            }
        }
    };

    loadAB(k0base);
    stsAB();
    __syncthreads();
    for (int ch = 1; ch < NCH; ch++) {
        loadAB(k0base + ch * 32);   // prefetch next chunk into regs
        compute();                  // compute current chunk from smem
        __syncthreads();
        stsAB();
        __syncthreads();
    }
    compute();

    // epilogue: c0:(g,2t) c1:(g,2t+1) c2:(g+8,2t) c3:(g+8,2t+1)
#pragma unroll
    for (int mt = 0; mt < 2; mt++) {
#pragma unroll
        for (int nt = 0; nt < 4; nt++) {
            int col = warp * 32 + nt * 8 + 2 * t;
            float bb0 = bias ? bias[col] : 0.f;
            float bb1 = bias ? bias[col + 1] : 0.f;
            int row = m0 + mt * 16 + g;
            *(float2*)(Cg + (size_t)row * FOUT + col) =
                make_float2(acc[mt][nt][0] + bb0, acc[mt][nt][1] + bb1);
            *(float2*)(Cg + (size_t)(row + 8) * FOUT + col) =
                make_float2(acc[mt][nt][2] + bb0, acc[mt][nt][3] + bb1);
        }
    }
}

// ---------------------------------------------------------------------------
// K0a: WpTh[n][k] = half(Wp[k][n])   (2048 x 128 -> 128 x 2048)
// ---------------------------------------------------------------------------
__global__ __launch_bounds__(256) void k_trWp(const float* __restrict__ Wp) {
    __shared__ float tb[32][33];
    const int k0 = blockIdx.x * 32, n0 = blockIdx.y * 32;
    const int tx = threadIdx.x & 31, ty0 = threadIdx.x >> 5;   // 32x8
#pragma unroll
    for (int dy = 0; dy < 32; dy += 8)
        tb[ty0 + dy][tx] = Wp[(size_t)(k0 + ty0 + dy) * FOUT + n0 + tx];
    __syncthreads();
#pragma unroll
    for (int dy = 0; dy < 32; dy += 8)
        g_WpTh[(size_t)(n0 + ty0 + dy) * FIN + k0 + tx] = __float2half_rn(tb[tx][ty0 + dy]);
}

// K0b: W1Th[z][f][k] = half(W1[z>>1][(z&1)*128 + k][f])
__global__ __launch_bounds__(256) void k_trW1(const float* __restrict__ W1) {
    __shared__ float tb[32][33];
    const int z  = blockIdx.z;
    const int k0 = blockIdx.x * 32, f0 = blockIdx.y * 32;
    const int tx = threadIdx.x & 31, ty0 = threadIdx.x >> 5;
    const float* src = W1 + ((size_t)(z >> 1) * 2 * FOUT + (z & 1) * FOUT) * FOUT;
#pragma unroll
    for (int dy = 0; dy < 32; dy += 8)
        tb[ty0 + dy][tx] = src[(size_t)(k0 + ty0 + dy) * FOUT + f0 + tx];
    __syncthreads();
#pragma unroll
    for (int dy = 0; dy < 32; dy += 8)
        g_W1Th[z][(size_t)(f0 + ty0 + dy) * FOUT + k0 + tx] = __float2half_rn(tb[tx][ty0 + dy]);
}

// ---------------------------------------------------------------------------
// K1: split-K partials of emb = x @ Wp
// ---------------------------------------------------------------------------
__global__ __launch_bounds__(128) void k_emb(const float* __restrict__ x) {
    const int m0 = blockIdx.x * 32;
    const int ks = blockIdx.y;
    gemm_fp16<KCHUNK / 32>(x, FIN, g_WpTh, FIN, ks * KCHUNK, m0, nullptr, g_part[ks]);
}

// K1b: g_emb = sum of 4 partials + bp
__global__ __launch_bounds__(256) void k_reduce4(const float* __restrict__ bp) {
    const int i = (blockIdx.x * 256 + threadIdx.x) * 4;
    float4 s = *(const float4*)(g_part[0] + i);
#pragma unroll
    for (int p = 1; p < KSPLIT; p++) {
        float4 v = *(const float4*)(g_part[p] + i);
        s.x += v.x; s.y += v.y; s.z += v.z; s.w += v.w;
    }
    float4 bv = *(const float4*)(bp + (i & 127));
    s.x += bv.x; s.y += bv.y; s.z += bv.z; s.w += bv.w;
    *(float4*)(g_emb + i) = s;
}

// ---------------------------------------------------------------------------
// K2: g_AC[z] = emb @ W1Th[z]^T  (+b1 on even z)
// ---------------------------------------------------------------------------
__global__ __launch_bounds__(128) void k_proj(const float* __restrict__ b1) {
    const int m0 = blockIdx.x * 32;
    const int z  = blockIdx.y;
    const float* bias = ((z & 1) == 0) ? (b1 + (size_t)(z >> 1) * FOUT) : nullptr;
    gemm_fp16<FOUT / 32>(g_emb, FOUT, g_W1Th[z], FOUT, 0, m0, bias, g_AC[z]);
}

// ---------------------------------------------------------------------------
// K3: pair scoring, f-split: 8 lanes per pair, 4 pairs per warp-iteration.
// S(i,k) = sum_f leaky(A[i][f]+C[k][f])*W2[h][f] + b2[h]
// out[b,h,j,i] = S(i, j+(j>=i)) for j<9;  out[b,h,9,:] = 0
// ---------------------------------------------------------------------------
__global__ __launch_bounds__(128) void k_pair4(const float* __restrict__ W2,
                                               const float* __restrict__ b2,
                                               float* __restrict__ out) {
    __shared__ __align__(16) float As[NNODES * 132];
    __shared__ __align__(16) float Cs[NNODES * 132];
    const int b = blockIdx.x, h = blockIdx.y;
    const int tid = threadIdx.x, lane = tid & 31, warp = tid >> 5;

    const float* Ap = g_AC[2 * h]     + (size_t)b * NNODES * FOUT;
    const float* Cp = g_AC[2 * h + 1] + (size_t)b * NNODES * FOUT;
    for (int e = tid; e < NNODES * 32; e += 128) {
        int r = e >> 5, c4 = e & 31;
        *(float4*)(As + r * 132 + c4 * 4) = *(const float4*)(Ap + r * FOUT + c4 * 4);
        *(float4*)(Cs + r * 132 + c4 * 4) = *(const float4*)(Cp + r * FOUT + c4 * 4);
    }
    const int sub = lane >> 3;       // pair-in-group 0..3
    const int fl  = lane & 7;        // f-slice 0..7 (16 floats each)
    float4 w2v[4];
#pragma unroll
    for (int j = 0; j < 4; j++) w2v[j] = *(const float4*)(W2 + h * FOUT + fl * 16 + j * 4);
    const float b2v = b2[h];
    __syncthreads();

    float* outp = out + ((size_t)b * NHEADS + h) * 100;
    for (int q = warp; q < 23; q += 4) {       // 23 groups of 4 pairs cover 90
        const int p = q * 4 + sub;
        float s = 0.f;
        int i = 0, kk = 0;
        if (p < 90) {
            i  = p / 9;
            kk = p - i * 9;                    // output row j
            const int k = kk + (kk >= i);      // source node
            const float* ar = As + i * 132 + fl * 16;
            const float* cr = Cs + k * 132 + fl * 16;
#pragma unroll
            for (int j = 0; j < 4; j++) {
                float4 av = *(const float4*)(ar + j * 4);
                float4 cv = *(const float4*)(cr + j * 4);
                float v0 = av.x + cv.x, v1 = av.y + cv.y;
                float v2 = av.z + cv.z, v3 = av.w + cv.w;
                v0 = (v0 > 0.f) ? v0 : 0.2f * v0;
                v1 = (v1 > 0.f) ? v1 : 0.2f * v1;
                v2 = (v2 > 0.f) ? v2 : 0.2f * v2;
                v3 = (v3 > 0.f) ? v3 : 0.2f * v3;
                s += v0 * w2v[j].x + v1 * w2v[j].y + v2 * w2v[j].z + v3 * w2v[j].w;
            }
        }
        s += __shfl_xor_sync(0xffffffffu, s, 4);
        s += __shfl_xor_sync(0xffffffffu, s, 2);
        s += __shfl_xor_sync(0xffffffffu, s, 1);
        if (p < 90 && fl == 0) outp[kk * 10 + i] = s + b2v;
    }
    if (tid < 10) outp[90 + tid] = 0.f;
}

// ---------------------------------------------------------------------------
// Launch. inputs: 0 object_features, 1 scene_geometry(unused), 2 Wp, 3 bp,
//                 4 W1, 5 b1, 6 W2, 7 b2, 8 d_max
// ---------------------------------------------------------------------------
extern "C" void kernel_launch(void* const* d_in, const int* in_sizes, int n_in,
                              void* d_out, int out_size) {
    const float* x  = (const float*)d_in[0];
    const float* Wp = (const float*)d_in[2];
    const float* bp = (const float*)d_in[3];
    const float* W1 = (const float*)d_in[4];
    const float* b1 = (const float*)d_in[5];
    const float* W2 = (const float*)d_in[6];
    const float* b2 = (const float*)d_in[7];
    float* out = (float*)d_out;

    dim3 gtw(FIN / 32, FOUT / 32);
    k_trWp<<<gtw, 256>>>(Wp);
    dim3 gt1(FOUT / 32, FOUT / 32, 16);
    k_trW1<<<gt1, 256>>>(W1);

    dim3 g1(MTOT / 32, KSPLIT);
    k_emb<<<g1, 128>>>(x);

    k_reduce4<<<MTOT * FOUT / (256 * 4), 256>>>(bp);

    dim3 g2(MTOT / 32, 16);
    k_proj<<<g2, 128>>>(b1);

    dim3 g3(NB, NHEADS);
    k_pair4<<<g3, 128>>>(W2, b2, out);
}